// round 1
// baseline (speedup 1.0000x reference)
#include <cuda_runtime.h>
#include <math.h>

#define BB 128
#define NN 256
#define MM (BB*NN)
#define KNBR 16
#define BN_SCALE_F 0.99999500003749969f

// ---------------- scratch (device globals; no allocation allowed) ----------
__device__ float g_U[MM * 256];
__device__ float g_V[MM * 256];
__device__ float g_h1[MM * 64];
__device__ float g_h2[MM * 128];
__device__ float g_h3[MM * 256];
__device__ int   g_idx[MM * KNBR];
__device__ float g_p[BB * 256];

// ---------------- kNN: one block per batch, thread per point ---------------
template<int D, int P>
__global__ __launch_bounds__(256, 1)
void knn_kernel(const float* __restrict__ X, int* __restrict__ idx_out) {
    extern __shared__ float sm[];
    float* Xs  = sm;            // [256 * P], P padded to mult of 4, pitch breaks 32-stride
    float* sqs = sm + NN * P;   // [256]
    const int b = blockIdx.x;
    const int t = threadIdx.x;
    const float* Xb = X + (size_t)b * NN * D;

    for (int e = t; e < NN * D; e += 256)
        Xs[(e / D) * P + (e % D)] = Xb[e];
    #pragma unroll
    for (int c = D; c < P; ++c) Xs[t * P + c] = 0.f;
    __syncthreads();

    constexpr int Q = P / 4;
    float4 xi[Q];
    #pragma unroll
    for (int q = 0; q < Q; ++q)
        xi[q] = *reinterpret_cast<const float4*>(&Xs[t * P + 4 * q]);
    float sq = 0.f;
    #pragma unroll
    for (int q = 0; q < Q; ++q)
        sq += xi[q].x * xi[q].x + xi[q].y * xi[q].y + xi[q].z * xi[q].z + xi[q].w * xi[q].w;
    sqs[t] = sq;
    __syncthreads();

    float bd[KNBR];
    int   bj[KNBR];
    #pragma unroll
    for (int s = 0; s < KNBR; ++s) { bd[s] = INFINITY; bj[s] = -1; }

    for (int j = 0; j < NN; ++j) {
        const float4* xj = reinterpret_cast<const float4*>(&Xs[j * P]);
        float dx = 0.f, dy = 0.f, dz = 0.f, dw = 0.f;
        #pragma unroll
        for (int q = 0; q < Q; ++q) {
            float4 v = xj[q];            // broadcast LDS.128
            dx += xi[q].x * v.x;
            dy += xi[q].y * v.y;
            dz += xi[q].z * v.z;
            dw += xi[q].w * v.w;
        }
        float dot = (dx + dy) + (dz + dw);
        float d2 = sq + sqs[j] - 2.f * dot;
        if (j != t && d2 < bd[KNBR - 1]) {
            float nd = d2; int nj = j;
            #pragma unroll
            for (int s = 0; s < KNBR; ++s) {   // stable sorted insert (lower idx wins ties)
                if (nd < bd[s]) {
                    float td = bd[s]; int tj = bj[s];
                    bd[s] = nd; bj[s] = nj; nd = td; nj = tj;
                }
            }
        }
    }
    #pragma unroll
    for (int s = 0; s < KNBR; ++s)
        idx_out[((size_t)b * NN + t) * KNBR + s] = bj[s];
}

// ---------------- layer-1 U/V GEMM (K=6, C=64): tiny, direct ---------------
__global__ __launch_bounds__(256)
void uv_gemm1_kernel(const float* __restrict__ X, const float* __restrict__ W,
                     float* __restrict__ U, float* __restrict__ V) {
    __shared__ float Ws[12][64];
    int t = threadIdx.x;
    for (int e = t; e < 12 * 64; e += 256) Ws[e / 64][e % 64] = W[e];
    __syncthreads();
    int m = blockIdx.x * 4 + (t >> 6);
    int c = t & 63;
    const float* x = X + (size_t)m * 6;
    float u = 0.f, v = 0.f;
    #pragma unroll
    for (int d = 0; d < 6; ++d) {
        float xd = x[d];
        u += xd * Ws[d][c];
        v += xd * Ws[6 + d][c];
    }
    U[(size_t)m * 64 + c] = u;
    V[(size_t)m * 64 + c] = v;
}

// ---------------- generic U/V GEMM: BM=64 BN=64 BK=16, 4x4/thread ----------
template<int K, int C>
__global__ __launch_bounds__(256)
void uv_gemm_kernel(const float* __restrict__ X, const float* __restrict__ W,
                    float* __restrict__ U, float* __restrict__ V) {
    __shared__ float As[16][65];
    __shared__ float Wt[16][64];
    __shared__ float Wb[16][64];
    const int t = threadIdx.x;
    const int m0 = blockIdx.x * 64;
    const int n0 = blockIdx.y * 64;
    const int tx = t & 15, ty = t >> 4;

    float accU[4][4] = {}, accV[4][4] = {};

    for (int k0 = 0; k0 < K; k0 += 16) {
        {
            int m = t >> 2;
            int kk = (t & 3) * 4;
            float4 xv = *reinterpret_cast<const float4*>(&X[(size_t)(m0 + m) * K + k0 + kk]);
            As[kk + 0][m] = xv.x; As[kk + 1][m] = xv.y;
            As[kk + 2][m] = xv.z; As[kk + 3][m] = xv.w;
        }
        {
            int k  = t >> 4;
            int nn = (t & 15) * 4;
            float4 wt = *reinterpret_cast<const float4*>(&W[(size_t)(k0 + k) * C + n0 + nn]);
            float4 wb = *reinterpret_cast<const float4*>(&W[(size_t)(K + k0 + k) * C + n0 + nn]);
            *reinterpret_cast<float4*>(&Wt[k][nn]) = wt;
            *reinterpret_cast<float4*>(&Wb[k][nn]) = wb;
        }
        __syncthreads();
        #pragma unroll
        for (int k = 0; k < 16; ++k) {
            float a[4];
            #pragma unroll
            for (int i = 0; i < 4; ++i) a[i] = As[k][ty * 4 + i];
            float4 wt = *reinterpret_cast<float4*>(&Wt[k][tx * 4]);
            float4 wb = *reinterpret_cast<float4*>(&Wb[k][tx * 4]);
            #pragma unroll
            for (int i = 0; i < 4; ++i) {
                accU[i][0] += a[i] * wt.x; accU[i][1] += a[i] * wt.y;
                accU[i][2] += a[i] * wt.z; accU[i][3] += a[i] * wt.w;
                accV[i][0] += a[i] * wb.x; accV[i][1] += a[i] * wb.y;
                accV[i][2] += a[i] * wb.z; accV[i][3] += a[i] * wb.w;
            }
        }
        __syncthreads();
    }
    #pragma unroll
    for (int i = 0; i < 4; ++i) {
        float4 ou = make_float4(accU[i][0], accU[i][1], accU[i][2], accU[i][3]);
        float4 ov = make_float4(accV[i][0], accV[i][1], accV[i][2], accV[i][3]);
        *reinterpret_cast<float4*>(&U[(size_t)(m0 + ty * 4 + i) * C + n0 + tx * 4]) = ou;
        *reinterpret_cast<float4*>(&V[(size_t)(m0 + ty * 4 + i) * C + n0 + tx * 4]) = ov;
    }
}

// ---------------- neighbor aggregation + BN + ReLU -------------------------
template<int C>
__global__ __launch_bounds__(256)
void agg_kernel(const float* __restrict__ U, const float* __restrict__ V,
                const int* __restrict__ idx, const float* __restrict__ bias,
                const float* __restrict__ g, const float* __restrict__ be,
                float* __restrict__ H) {
    constexpr int PPB = 256 / C;
    __shared__ int sidx[PPB * KNBR];
    const int p0 = blockIdx.x * PPB;
    const int t = threadIdx.x;
    if (t < PPB * KNBR) sidx[t] = idx[(size_t)p0 * KNBR + t];
    __syncthreads();
    const int lp = t / C, c = t % C;
    const int pt = p0 + lp;
    const int b = pt >> 8;
    const float* Vb = V + ((size_t)(b << 8)) * C;
    float u = U[(size_t)pt * C + c];
    float v = V[(size_t)pt * C + c];
    float mx = -INFINITY, mn = INFINITY;
    #pragma unroll
    for (int k = 0; k < KNBR; ++k) {
        float val = Vb[(size_t)sidx[lp * KNBR + k] * C + c];
        mx = fmaxf(mx, val);
        mn = fminf(mn, val);
    }
    float a = g[c] * BN_SCALE_F;
    float m = (a >= 0.f) ? mx : mn;   // monotone affine+relu commutes with max
    float h = fmaf(a, u - v + m + bias[c], be[c]);
    H[(size_t)pt * C + c] = fmaxf(h, 0.f);
}

// ---------------- global max pool ------------------------------------------
template<int C>
__global__ __launch_bounds__(256)
void pool_kernel(const float* __restrict__ H, float* __restrict__ Pp) {
    const int b = blockIdx.x, c = threadIdx.x;
    float mx = -INFINITY;
    for (int n = 0; n < NN; ++n)
        mx = fmaxf(mx, H[((size_t)(b * NN + n)) * C + c]);
    Pp[b * C + c] = mx;
}

// ---------------- FC head --------------------------------------------------
__global__ __launch_bounds__(256)
void head_kernel(const float* __restrict__ Pp, const float* __restrict__ Wf1,
                 const float* __restrict__ bf1, const float* __restrict__ gf,
                 const float* __restrict__ bef, const float* __restrict__ Wf2,
                 const float* __restrict__ bf2, float* __restrict__ out) {
    __shared__ float ps[256];
    __shared__ float fs[128];
    const int b = blockIdx.x, t = threadIdx.x;
    ps[t] = Pp[b * 256 + t];
    __syncthreads();
    if (t < 128) {
        float acc = bf1[t];
        for (int r = 0; r < 256; ++r) acc += ps[r] * Wf1[r * 128 + t];
        float a = gf[t] * BN_SCALE_F;
        fs[t] = fmaxf(fmaf(a, acc, bef[t]), 0.f);
    }
    __syncthreads();
    if (t < 12) {
        float acc = bf2[t];
        for (int j = 0; j < 128; ++j) acc += fs[j] * Wf2[j * 12 + t];
        out[b * 12 + t] = acc;
    }
}

// ---------------- launch ----------------------------------------------------
extern "C" void kernel_launch(void* const* d_in, const int* in_sizes, int n_in,
                              void* d_out, int out_size) {
    const float* x   = (const float*)d_in[0];
    const float* W1  = (const float*)d_in[1];
    const float* b1  = (const float*)d_in[2];
    const float* g1  = (const float*)d_in[3];
    const float* be1 = (const float*)d_in[4];
    const float* W2  = (const float*)d_in[5];
    const float* b2  = (const float*)d_in[6];
    const float* g2  = (const float*)d_in[7];
    const float* be2 = (const float*)d_in[8];
    const float* W3  = (const float*)d_in[9];
    const float* b3  = (const float*)d_in[10];
    const float* g3  = (const float*)d_in[11];
    const float* be3 = (const float*)d_in[12];
    const float* Wf1 = (const float*)d_in[13];
    const float* bf1 = (const float*)d_in[14];
    const float* gf  = (const float*)d_in[15];
    const float* bef = (const float*)d_in[16];
    const float* Wf2 = (const float*)d_in[17];
    const float* bf2 = (const float*)d_in[18];
    float* out = (float*)d_out;

    float *U, *V, *h1, *h2, *h3, *p;
    int* idx;
    cudaGetSymbolAddress((void**)&U,  g_U);
    cudaGetSymbolAddress((void**)&V,  g_V);
    cudaGetSymbolAddress((void**)&h1, g_h1);
    cudaGetSymbolAddress((void**)&h2, g_h2);
    cudaGetSymbolAddress((void**)&h3, g_h3);
    cudaGetSymbolAddress((void**)&idx, g_idx);
    cudaGetSymbolAddress((void**)&p,  g_p);

    const int smem6   = (NN * 8   + NN) * 4;
    const int smem64  = (NN * 68  + NN) * 4;
    const int smem128 = (NN * 132 + NN) * 4;
    cudaFuncSetAttribute(knn_kernel<64, 68>,
                         cudaFuncAttributeMaxDynamicSharedMemorySize, smem64);
    cudaFuncSetAttribute(knn_kernel<128, 132>,
                         cudaFuncAttributeMaxDynamicSharedMemorySize, smem128);

    // ---- layer 1: D=6 -> C=64 ----
    knn_kernel<6, 8><<<BB, 256, smem6>>>(x, idx);
    uv_gemm1_kernel<<<MM / 4, 256>>>(x, W1, U, V);
    agg_kernel<64><<<MM / 4, 256>>>(U, V, idx, b1, g1, be1, h1);

    // ---- layer 2: D=64 -> C=128 ----
    knn_kernel<64, 68><<<BB, 256, smem64>>>(h1, idx);
    uv_gemm_kernel<64, 128><<<dim3(MM / 64, 2), 256>>>(h1, W2, U, V);
    agg_kernel<128><<<MM / 2, 256>>>(U, V, idx, b2, g2, be2, h2);

    // ---- layer 3: D=128 -> C=256 ----
    knn_kernel<128, 132><<<BB, 256, smem128>>>(h2, idx);
    uv_gemm_kernel<128, 256><<<dim3(MM / 64, 4), 256>>>(h2, W3, U, V);
    agg_kernel<256><<<MM, 256>>>(U, V, idx, b3, g3, be3, h3);

    // ---- pool + head ----
    pool_kernel<256><<<BB, 256>>>(h3, p);
    head_kernel<<<BB, 256>>>(p, Wf1, bf1, gf, bef, Wf2, bf2, out);
}